// round 14
// baseline (speedup 1.0000x reference)
#include <cuda_runtime.h>
#include <math.h>

#define BATCH 8
#define FEAT 512
#define NUM 512
#define KK 32
#define NSPLIT 8
#define NBLK 296      // 2 x 148 SMs
#define P2_UNITS 512  // 8 n-chunks x 8 f-tiles x 8 batches

typedef unsigned long long ull;

// 1/sqrt(512): global L2 scale is exact (512 unit-norm rows per half)
#define GSC 0.04419417382415922f

// ---------------- device scratch (static, allocation-free) ----------------
__device__ float g_a[BATCH * NUM * KK];               // a[b][n][k]
__device__ float g_axp[NSPLIT * BATCH * FEAT * KK];   // partial ax  [s][b][f][k]
__device__ float g_ax2p[NSPLIT * BATCH * FEAT * KK];  // partial ax2 [s][b][f][k]
__device__ float g_asumt[BATCH * KK * 32];            // asum partials [b][k][tile]
__device__ unsigned g_cnt = 0;                        // barrier counter (self-resets)
__device__ unsigned g_gen = 0;                        // barrier generation (monotonic)
__device__ unsigned g_work = 0;                       // phase-2 dynamic unit counter

__device__ __forceinline__ float wsum(float v) {
#pragma unroll
    for (int o = 16; o; o >>= 1) v += __shfl_xor_sync(0xffffffffu, v, o);
    return v;
}
__device__ __forceinline__ float wmax(float v) {
#pragma unroll
    for (int o = 16; o; o >>= 1) v = fmaxf(v, __shfl_xor_sync(0xffffffffu, v, o));
    return v;
}

// packed f32x2 helpers (sm_100+)
__device__ __forceinline__ ull pk(float lo, float hi) {
    ull r;
    asm("mov.b64 %0, {%1, %2};" : "=l"(r) : "f"(lo), "f"(hi));
    return r;
}
__device__ __forceinline__ void upk(float& lo, float& hi, ull v) {
    asm("mov.b64 {%0, %1}, %2;" : "=f"(lo), "=f"(hi) : "l"(v));
}
__device__ __forceinline__ void ffma2(ull& d, ull a, ull b) {
    asm("fma.rn.f32x2 %0, %1, %2, %0;" : "+l"(d) : "l"(a), "l"(b));
}
__device__ __forceinline__ ull fmul2(ull a, ull b) {
    ull r;
    asm("mul.rn.f32x2 %0, %1, %2;" : "=l"(r) : "l"(a), "l"(b));
    return r;
}
__device__ __forceinline__ float fold(ull v) {
    float lo, hi;
    upk(lo, hi, v);
    return lo + hi;
}

// Replay-safe grid barrier (volatile-load polling, monotonic generation).
__device__ __forceinline__ void gridbar() {
    __syncthreads();
    if (threadIdx.x == 0) {
        __threadfence();
        unsigned gen = *((volatile unsigned*)&g_gen);
        if (atomicAdd(&g_cnt, 1u) == NBLK - 1u) {
            *((volatile unsigned*)&g_cnt) = 0u;
            __threadfence();
            atomicAdd(&g_gen, 1u);
        } else {
            while (*((volatile unsigned*)&g_gen) == gen) __nanosleep(64);
        }
        __threadfence();
    }
    __syncthreads();
}

// shared-memory phase union
struct P1 {
    float X4[128 * 16];        // [f][n16]; 16B rows -> LDS128 broadcast     (8KB)
    float W_s[32 * 129];       // [k][128f+pad]; lane=k stride 129 cf      (16.1KB)
    float red_f[8 * 32 * 17];  // f-partial logits [warp][lane][16n+pad]    (17KB)
    float asr[8 * 33];         // asum cross-warp                            (1KB)
};
struct P2 {
    ull At[32 * 33];           // a TRANSPOSED [k][n-pair]; stride 33 (odd)  (8.4KB)
    ull Xs[64 * 34];           // x [f][n-pair]; stride 34 (16B-align f4)   (17.4KB)
    float4 F1[128 * 4];        // nq=1 fold buffer, ax  [thread][j]           (8KB)
    float4 F2[128 * 4];        // nq=1 fold buffer, ax2 [thread][j]           (8KB)
};
union SMU {
    P1 p1;
    P2 p2;
};

// ---------------- single kernel: softmax -> bar -> gemm -> bar -> fv ---------
__global__ __launch_bounds__(256, 2) void k_all(const float* __restrict__ x,
                                                const float* __restrict__ W,
                                                const float* __restrict__ bias,
                                                const float* __restrict__ mu,
                                                const float* __restrict__ sigma,
                                                float* __restrict__ out) {
    __shared__ __align__(16) SMU sm;
    __shared__ int s_unit;
    const int tid  = threadIdx.x;
    const int w    = tid >> 5;
    const int lane = tid & 31;
    const int bx   = blockIdx.x;

    // reset phase-2 work counter for this replay (ordered before use by gridbar)
    if (bx == 0 && tid == 0) *((volatile unsigned*)&g_work) = 0u;

    // ================= PHASE 1: logits + softmax + asum =======================
    if (bx < 256) {
        const int b    = bx >> 5;
        const int tile = bx & 31;
        const int n0   = tile * 16;

        ull acc[8] = {0, 0, 0, 0, 0, 0, 0, 0};

        for (int t = 0; t < 4; t++) {
            const int fb = t * 128;
            __syncthreads();
#pragma unroll
            for (int i = 0; i < 16; i++) {
                int idx = tid + i * 256;
                int k = idx >> 7, fl = idx & 127;
                sm.p1.W_s[k * 129 + fl] = W[k * FEAT + fb + fl];
            }
#pragma unroll
            for (int i = 0; i < 2; i++) {
                int idx = tid + i * 256;
                int fr = idx >> 2, c4 = (idx & 3) * 4;
                float4 v = *reinterpret_cast<const float4*>(
                    &x[((size_t)b * FEAT + fb + fr) * NUM + n0 + c4]);
                *reinterpret_cast<float4*>(&sm.p1.X4[fr * 16 + c4]) = v;
            }
            __syncthreads();
            const int fw = w * 16;
#pragma unroll 4
            for (int fi = 0; fi < 16; fi++) {
                const int fl = fw + fi;
                float wv = sm.p1.W_s[lane * 129 + fl];           // LDS32 cf
                ull   wp = pk(wv, wv);
                const ulonglong2* xr = reinterpret_cast<const ulonglong2*>(&sm.p1.X4[fl * 16]);
                ulonglong2 xa = xr[0];                            // LDS128 bc
                ulonglong2 xb = xr[1];
                ffma2(acc[0], wp, xa.x);
                ffma2(acc[1], wp, xa.y);
                ffma2(acc[2], wp, xb.x);
                ffma2(acc[3], wp, xb.y);
                xa = xr[2];
                xb = xr[3];
                ffma2(acc[4], wp, xa.x);
                ffma2(acc[5], wp, xa.y);
                ffma2(acc[6], wp, xb.x);
                ffma2(acc[7], wp, xb.y);
            }
        }

        __syncthreads();
        {
            float* r = &sm.p1.red_f[(w * 32 + lane) * 17];
#pragma unroll
            for (int j = 0; j < 8; j++) {
                float f0, f1;
                upk(f0, f1, acc[j]);
                r[2 * j]     = f0;
                r[2 * j + 1] = f1;
            }
        }
        __syncthreads();

        {
            float l0 = 0.f, l1 = 0.f;
#pragma unroll
            for (int g = 0; g < 8; g++) {
                const float* r = &sm.p1.red_f[(g * 32 + lane) * 17 + 2 * w];
                l0 += r[0];
                l1 += r[1];
            }
            const float bv = bias[lane];
            float pa;
            {
                float lg = l0 + bv;
                float m = wmax(lg);
                float e = __expf(lg - m);
                float s = wsum(e);
                float a = e / s;
                g_a[((size_t)b * NUM + n0 + 2 * w) * KK + lane] = a;
                pa = a;
            }
            {
                float lg = l1 + bv;
                float m = wmax(lg);
                float e = __expf(lg - m);
                float s = wsum(e);
                float a = e / s;
                g_a[((size_t)b * NUM + n0 + 2 * w + 1) * KK + lane] = a;
                pa += a;
            }
            sm.p1.asr[w * 33 + lane] = pa;
        }
        __syncthreads();
        if (tid < 32) {
            float s = 0.f;
#pragma unroll
            for (int g = 0; g < 8; g++) s += sm.p1.asr[g * 33 + tid];
            g_asumt[((size_t)b * KK + tid) * 32 + tile] = s;
        }
    }

    gridbar();

    // ================= PHASE 2 (dynamic): square-tiled GEMM + smem nq-fold ====
    // unit u: n-chunk c = u&7 (64 n), f-tile ft = (u>>3)&7 (64 f), b = u>>6.
    // warps: fh = w&1, kh = (w>>1)&1, nq = w>>2. thread = 4f x 4k x n-pairs.
    // nq=1 results folded into nq=0's through smem -> ONE partial per n-chunk.
    {
        const int fh = w & 1;
        const int kh = (w >> 1) & 1;
        const int nq = w >> 2;
        const int fgl = (fh << 5) + (lane >> 2);   // f local base (j adds 8)
        const int kbase = (kh << 4) + (lane & 3) * 4;

        for (;;) {
            __syncthreads();               // prior unit fully consumed
            if (tid == 0) s_unit = (int)atomicAdd(&g_work, 1u);
            __syncthreads();
            const int u = s_unit;
            if (u >= P2_UNITS) break;
            const int c  = u & 7;
            const int ft = (u >> 3) & 7;
            const int b  = u >> 6;
            const int f0 = ft * 64;
            const int n0 = c * 64;

            // stage A TRANSPOSED: At[k][n] (float view stride 66)
            float* Atf = reinterpret_cast<float*>(sm.p2.At);
#pragma unroll
            for (int i = 0; i < 2; i++) {
                int idx = tid + i * 256;
                int nl = idx >> 3, kq = (idx & 7) * 4;
                float4 v = *reinterpret_cast<const float4*>(
                    &g_a[((size_t)b * NUM + n0 + nl) * KK + kq]);
                Atf[(kq + 0) * 66 + nl] = v.x;
                Atf[(kq + 1) * 66 + nl] = v.y;
                Atf[(kq + 2) * 66 + nl] = v.z;
                Atf[(kq + 3) * 66 + nl] = v.w;
            }
            // stage X rows [64 f][64 n] (float view stride 68)
            float* Xsf = reinterpret_cast<float*>(sm.p2.Xs);
#pragma unroll
            for (int i = 0; i < 4; i++) {
                int idx = tid + i * 256;
                int fr = idx >> 4, nc = (idx & 15) * 4;
                float4 v = *reinterpret_cast<const float4*>(
                    &x[((size_t)b * FEAT + f0 + fr) * NUM + n0 + nc]);
                *reinterpret_cast<float4*>(&Xsf[fr * 68 + nc]) = v;
            }
            __syncthreads();

            ull ac1[4][4], ac2[4][4];
#pragma unroll
            for (int j = 0; j < 4; j++)
#pragma unroll
                for (int m = 0; m < 4; m++) { ac1[j][m] = 0ULL; ac2[j][m] = 0ULL; }

            const ull* Xrow = &sm.p2.Xs[(size_t)fgl * 34 + nq * 16];
            const ull* Arow = &sm.p2.At[(size_t)kbase * 33 + nq * 16];

#pragma unroll 4
            for (int np = 0; np < 16; np++) {
                ull x0 = Xrow[np];             // LDS64 cf (stride 34)
                ull x1 = Xrow[np + 8 * 34];
                ull x2 = Xrow[np + 16 * 34];
                ull x3 = Xrow[np + 24 * 34];
                ull a0 = Arow[np];             // LDS64 cf (stride 33)
                ull a1 = Arow[np + 33];
                ull a2 = Arow[np + 66];
                ull a3 = Arow[np + 99];
                ull q0 = fmul2(x0, x0);
                ull q1 = fmul2(x1, x1);
                ull q2 = fmul2(x2, x2);
                ull q3 = fmul2(x3, x3);
                ffma2(ac1[0][0], a0, x0);  ffma2(ac2[0][0], a0, q0);
                ffma2(ac1[0][1], a1, x0);  ffma2(ac2[0][1], a1, q0);
                ffma2(ac1[0][2], a2, x0);  ffma2(ac2[0][2], a2, q0);
                ffma2(ac1[0][3], a3, x0);  ffma2(ac2[0][3], a3, q0);
                ffma2(ac1[1][0], a0, x1);  ffma2(ac2[1][0], a0, q1);
                ffma2(ac1[1][1], a1, x1);  ffma2(ac2[1][1], a1, q1);
                ffma2(ac1[1][2], a2, x1);  ffma2(ac2[1][2], a2, q1);
                ffma2(ac1[1][3], a3, x1);  ffma2(ac2[1][3], a3, q1);
                ffma2(ac1[2][0], a0, x2);  ffma2(ac2[2][0], a0, q2);
                ffma2(ac1[2][1], a1, x2);  ffma2(ac2[2][1], a1, q2);
                ffma2(ac1[2][2], a2, x2);  ffma2(ac2[2][2], a2, q2);
                ffma2(ac1[2][3], a3, x2);  ffma2(ac2[2][3], a3, q2);
                ffma2(ac1[3][0], a0, x3);  ffma2(ac2[3][0], a0, q3);
                ffma2(ac1[3][1], a1, x3);  ffma2(ac2[3][1], a1, q3);
                ffma2(ac1[3][2], a2, x3);  ffma2(ac2[3][2], a2, q3);
                ffma2(ac1[3][3], a3, x3);  ffma2(ac2[3][3], a3, q3);
            }

            // fold even/odd n halves of each acc into float4s
            float4 v1[4], v2[4];
#pragma unroll
            for (int j = 0; j < 4; j++) {
                v1[j].x = fold(ac1[j][0]); v1[j].y = fold(ac1[j][1]);
                v1[j].z = fold(ac1[j][2]); v1[j].w = fold(ac1[j][3]);
                v2[j].x = fold(ac2[j][0]); v2[j].y = fold(ac2[j][1]);
                v2[j].z = fold(ac2[j][2]); v2[j].w = fold(ac2[j][3]);
            }

            // nq=1 -> smem; nq=0 adds partner's half and stores ONE partial (s=c)
            __syncthreads();               // At/Xs reads done; F1/F2 may overlay
            if (nq == 1) {
                const int tt = tid - 128;
#pragma unroll
                for (int j = 0; j < 4; j++) {
                    sm.p2.F1[tt * 4 + j] = v1[j];   // STS.128, tid-contiguous cf
                    sm.p2.F2[tt * 4 + j] = v2[j];
                }
            }
            __syncthreads();
            if (nq == 0) {
#pragma unroll
                for (int j = 0; j < 4; j++) {
                    float4 p1 = sm.p2.F1[tid * 4 + j];   // LDS128 cf
                    float4 p2 = sm.p2.F2[tid * 4 + j];
                    v1[j].x += p1.x; v1[j].y += p1.y; v1[j].z += p1.z; v1[j].w += p1.w;
                    v2[j].x += p2.x; v2[j].y += p2.y; v2[j].z += p2.z; v2[j].w += p2.w;
                    const int f = f0 + fgl + 8 * j;
                    const size_t base =
                        (((size_t)c * BATCH + b) * FEAT + f) * KK + kbase;
                    *reinterpret_cast<float4*>(&g_axp[base])  = v1[j];
                    *reinterpret_cast<float4*>(&g_ax2p[base]) = v2[j];
                }
            }
        }
    }

    gridbar();

    // ================= PHASE 3: fisher vectors + rownorm + const scale ========
    if (bx < 256) {
        const int b      = bx >> 5;
        const int fgbase = (bx & 31) * 2;

        // asum[b][k]: 32 contiguous partials -> 8x LDG.128
        float asv = 0.f;
        {
            const float4* p = reinterpret_cast<const float4*>(&g_asumt[((size_t)b * KK + lane) * 32]);
#pragma unroll
            for (int q = 0; q < 8; q++) {
                float4 v = p[q];
                asv += (v.x + v.y) + (v.z + v.w);
            }
        }

#pragma unroll
        for (int j = 0; j < 2; j++) {
            const int f = (fgbase + j) * 8 + w;
            float ax = 0.f, ax2 = 0.f;
#pragma unroll
            for (int s = 0; s < NSPLIT; s++) {
                size_t po = (((size_t)s * BATCH + b) * FEAT + f) * KK + lane;
                ax  += g_axp[po];
                ax2 += g_ax2p[po];
            }
            float muv = mu[f * KK + lane];
            float sg  = sigma[f * KK + lane];
            float fv1 = (ax - muv * asv) / sg;
            float fv2 = (ax2 - 2.f * muv * ax + muv * muv * asv) / (sg * sg) - asv;

            float n1 = sqrtf(wsum(fv1 * fv1));
            float n2 = sqrtf(wsum(fv2 * fv2));
            float v1 = fv1 / fmaxf(n1, 1e-12f) * GSC;
            float v2 = fv2 / fmaxf(n2, 1e-12f) * GSC;

            const size_t ob = (size_t)b * 2 * FEAT * KK;
            out[ob + (size_t)f * KK + lane]             = v1;
            out[ob + FEAT * KK + (size_t)f * KK + lane] = v2;
        }
    }
}

// ---------------- launch -----------------------------------------------------
extern "C" void kernel_launch(void* const* d_in, const int* in_sizes, int n_in,
                              void* d_out, int out_size) {
    (void)in_sizes; (void)n_in; (void)out_size;
    const float* x     = (const float*)d_in[0];
    const float* W     = (const float*)d_in[1];
    const float* bias  = (const float*)d_in[2];
    const float* mu    = (const float*)d_in[3];
    const float* sigma = (const float*)d_in[4];
    float* out = (float*)d_out;

    k_all<<<NBLK, 256>>>(x, W, bias, mu, sigma, out);
}

// round 15
// speedup vs baseline: 1.0728x; 1.0728x over previous
#include <cuda_runtime.h>
#include <math.h>

#define BATCH 8
#define FEAT 512
#define NUM 512
#define KK 32
#define NSPLIT 16
#define NBLK 256      // all co-resident at occ 2 (148 SMs)
#define P2_UNITS 512

typedef unsigned long long ull;

// 1/sqrt(512): global L2 scale is exact (512 unit-norm rows per half)
#define GSC 0.04419417382415922f

// ---- dynamic smem layout (bytes) -------------------------------------------
// P1: W resident 4 chunks [32][129]        @      0 .. 66048
//     X double buffer 2 x [128][16]        @  66048 .. 82432
//     red_f [8][32][17]                    @  82432 .. 99840
//     asr   [8][33]                        @  99840 .. 100896
// P2 (overlays P1's W region, time-separated):
//     At0 [32][33] ull                     @      0 ..  8448
//     Xs0 [64][34] ull                     @   8448 .. 25856
//     At1                                  @  25856 .. 34304
//     Xs1                                  @  34304 .. 51712
#define SMEM_BYTES 100896

// ---------------- device scratch (static, allocation-free) ----------------
__device__ float g_a[BATCH * NUM * KK];               // a[b][n][k]
__device__ float g_axp[NSPLIT * BATCH * FEAT * KK];   // partial ax  [s][b][f][k]
__device__ float g_ax2p[NSPLIT * BATCH * FEAT * KK];  // partial ax2 [s][b][f][k]
__device__ float g_asumt[BATCH * KK * 32];            // asum partials [b][k][tile]
__device__ unsigned g_cnt = 0;                        // barrier counter (self-resets)
__device__ unsigned g_gen = 0;                        // barrier generation (monotonic)

__device__ __forceinline__ float wsum(float v) {
#pragma unroll
    for (int o = 16; o; o >>= 1) v += __shfl_xor_sync(0xffffffffu, v, o);
    return v;
}
__device__ __forceinline__ float wmax(float v) {
#pragma unroll
    for (int o = 16; o; o >>= 1) v = fmaxf(v, __shfl_xor_sync(0xffffffffu, v, o));
    return v;
}

// packed f32x2 helpers (sm_100+)
__device__ __forceinline__ ull pk(float lo, float hi) {
    ull r;
    asm("mov.b64 %0, {%1, %2};" : "=l"(r) : "f"(lo), "f"(hi));
    return r;
}
__device__ __forceinline__ void upk(float& lo, float& hi, ull v) {
    asm("mov.b64 {%0, %1}, %2;" : "=f"(lo), "=f"(hi) : "l"(v));
}
__device__ __forceinline__ void ffma2(ull& d, ull a, ull b) {
    asm("fma.rn.f32x2 %0, %1, %2, %0;" : "+l"(d) : "l"(a), "l"(b));
}
__device__ __forceinline__ ull fmul2(ull a, ull b) {
    ull r;
    asm("mul.rn.f32x2 %0, %1, %2;" : "=l"(r) : "l"(a), "l"(b));
    return r;
}
__device__ __forceinline__ float fold(ull v) {
    float lo, hi;
    upk(lo, hi, v);
    return lo + hi;
}

// Replay-safe grid barrier (volatile-load polling, monotonic generation).
__device__ __forceinline__ void gridbar() {
    __syncthreads();
    if (threadIdx.x == 0) {
        __threadfence();
        unsigned gen = *((volatile unsigned*)&g_gen);
        if (atomicAdd(&g_cnt, 1u) == NBLK - 1u) {
            *((volatile unsigned*)&g_cnt) = 0u;
            __threadfence();
            atomicAdd(&g_gen, 1u);
        } else {
            while (*((volatile unsigned*)&g_gen) == gen) __nanosleep(64);
        }
        __threadfence();
    }
    __syncthreads();
}

// ---- phase-2 helpers (r13-identical compute) --------------------------------
__device__ __forceinline__ void p2_stage(char* smx, int at_off, int xs_off,
                                         const float* __restrict__ x,
                                         int b, int f0, int n0, int tid,
                                         bool stage_x) {
    float* Atf = reinterpret_cast<float*>(smx + at_off);
#pragma unroll
    for (int i = 0; i < 2; i++) {
        int idx = tid + i * 256;
        int nl = idx >> 3, kq = (idx & 7) * 4;
        float4 v = *reinterpret_cast<const float4*>(
            &g_a[((size_t)b * NUM + n0 + nl) * KK + kq]);
        Atf[(kq + 0) * 66 + nl] = v.x;
        Atf[(kq + 1) * 66 + nl] = v.y;
        Atf[(kq + 2) * 66 + nl] = v.z;
        Atf[(kq + 3) * 66 + nl] = v.w;
    }
    if (stage_x) {
        float* Xsf = reinterpret_cast<float*>(smx + xs_off);
#pragma unroll
        for (int i = 0; i < 4; i++) {
            int idx = tid + i * 256;
            int fr = idx >> 4, nc = (idx & 15) * 4;
            float4 v = *reinterpret_cast<const float4*>(
                &x[((size_t)b * FEAT + f0 + fr) * NUM + n0 + nc]);
            *reinterpret_cast<float4*>(&Xsf[fr * 68 + nc]) = v;
        }
    }
}

__device__ __forceinline__ void p2_compute(char* smx, int at_off, int xs_off,
                                           int c, int f0, int b,
                                           int fgl, int kbase, int nq) {
    const ull* At = reinterpret_cast<const ull*>(smx + at_off);
    const ull* Xs = reinterpret_cast<const ull*>(smx + xs_off);

    ull ac1[4][4], ac2[4][4];
#pragma unroll
    for (int j = 0; j < 4; j++)
#pragma unroll
        for (int m = 0; m < 4; m++) { ac1[j][m] = 0ULL; ac2[j][m] = 0ULL; }

    const ull* Xrow = &Xs[(size_t)fgl * 34 + nq * 16];
    const ull* Arow = &At[(size_t)kbase * 33 + nq * 16];

#pragma unroll 4
    for (int np = 0; np < 16; np++) {
        ull x0 = Xrow[np];             // LDS64 cf (stride 34)
        ull x1 = Xrow[np + 8 * 34];
        ull x2 = Xrow[np + 16 * 34];
        ull x3 = Xrow[np + 24 * 34];
        ull a0 = Arow[np];             // LDS64 cf (stride 33)
        ull a1 = Arow[np + 33];
        ull a2 = Arow[np + 66];
        ull a3 = Arow[np + 99];
        ull q0 = fmul2(x0, x0);
        ull q1 = fmul2(x1, x1);
        ull q2 = fmul2(x2, x2);
        ull q3 = fmul2(x3, x3);
        ffma2(ac1[0][0], a0, x0);  ffma2(ac2[0][0], a0, q0);
        ffma2(ac1[0][1], a1, x0);  ffma2(ac2[0][1], a1, q0);
        ffma2(ac1[0][2], a2, x0);  ffma2(ac2[0][2], a2, q0);
        ffma2(ac1[0][3], a3, x0);  ffma2(ac2[0][3], a3, q0);
        ffma2(ac1[1][0], a0, x1);  ffma2(ac2[1][0], a0, q1);
        ffma2(ac1[1][1], a1, x1);  ffma2(ac2[1][1], a1, q1);
        ffma2(ac1[1][2], a2, x1);  ffma2(ac2[1][2], a2, q1);
        ffma2(ac1[1][3], a3, x1);  ffma2(ac2[1][3], a3, q1);
        ffma2(ac1[2][0], a0, x2);  ffma2(ac2[2][0], a0, q2);
        ffma2(ac1[2][1], a1, x2);  ffma2(ac2[2][1], a1, q2);
        ffma2(ac1[2][2], a2, x2);  ffma2(ac2[2][2], a2, q2);
        ffma2(ac1[2][3], a3, x2);  ffma2(ac2[2][3], a3, q2);
        ffma2(ac1[3][0], a0, x3);  ffma2(ac2[3][0], a0, q3);
        ffma2(ac1[3][1], a1, x3);  ffma2(ac2[3][1], a1, q3);
        ffma2(ac1[3][2], a2, x3);  ffma2(ac2[3][2], a2, q3);
        ffma2(ac1[3][3], a3, x3);  ffma2(ac2[3][3], a3, q3);
    }

    const int split = c * 2 + nq;
#pragma unroll
    for (int j = 0; j < 4; j++) {
        const int f = f0 + fgl + 8 * j;
        const size_t base = (((size_t)split * BATCH + b) * FEAT + f) * KK + kbase;
        float4 v1, v2;
        v1.x = fold(ac1[j][0]); v1.y = fold(ac1[j][1]);
        v1.z = fold(ac1[j][2]); v1.w = fold(ac1[j][3]);
        v2.x = fold(ac2[j][0]); v2.y = fold(ac2[j][1]);
        v2.z = fold(ac2[j][2]); v2.w = fold(ac2[j][3]);
        *reinterpret_cast<float4*>(&g_axp[base])  = v1;
        *reinterpret_cast<float4*>(&g_ax2p[base]) = v2;
    }
}

// ---------------- single kernel: softmax -> bar -> gemm -> bar -> fv ---------
__global__ __launch_bounds__(256, 2) void k_all(const float* __restrict__ x,
                                                const float* __restrict__ W,
                                                const float* __restrict__ bias,
                                                const float* __restrict__ mu,
                                                const float* __restrict__ sigma,
                                                float* __restrict__ out) {
    extern __shared__ __align__(16) char smx[];
    float* Wf   = reinterpret_cast<float*>(smx);          // [4 chunks][32][129]
    float* X4   = Wf + 16512;                             // 2 x [128][16]
    float* redf = Wf + 20608;                             // [8][32][17]
    float* asr  = Wf + 24960;                             // [8][33]

    const int tid  = threadIdx.x;
    const int w    = tid >> 5;
    const int lane = tid & 31;
    const int bx   = blockIdx.x;

    // phase-2 static units: u0 = bx, u1 = bx + 256
    const int c0 = bx & 7,        ft0 = (bx >> 3) & 7,  b0 = bx >> 6;
    const int u1 = bx + 256;
    const int c1 = u1 & 7,        ft1 = (u1 >> 3) & 7,  b1 = u1 >> 6;

    // ================= PHASE 1: logits + softmax + asum =======================
    // b = bx>>5, 16-n tile = bx&31. W resident; X double-buffered.
    {
        const int b    = bx >> 5;
        const int tile = bx & 31;
        const int n0   = tile * 16;

        // stage ALL W once: 16384 floats, coalesced LDG, conflict-free STS
#pragma unroll
        for (int i = 0; i < 64; i++) {
            int idx = tid + i * 256;
            int k = idx >> 9, f = idx & 511;
            Wf[(f >> 7) * 4128 + k * 129 + (f & 127)] = W[k * FEAT + f];
        }
        // stage X chunk 0 into buffer 0
#pragma unroll
        for (int i = 0; i < 2; i++) {
            int idx = tid + i * 256;
            int fr = idx >> 2, c4 = (idx & 3) * 4;
            float4 v = *reinterpret_cast<const float4*>(
                &x[((size_t)b * FEAT + fr) * NUM + n0 + c4]);
            *reinterpret_cast<float4*>(&X4[fr * 16 + c4]) = v;
        }

        ull acc[8] = {0, 0, 0, 0, 0, 0, 0, 0};

        for (int t = 0; t < 4; t++) {
            __syncthreads();   // buffer t&1 staged; previous compute done
            if (t < 3) {
                const int fb = (t + 1) * 128;
                float* xb = &X4[((t + 1) & 1) * 2048];
#pragma unroll
                for (int i = 0; i < 2; i++) {
                    int idx = tid + i * 256;
                    int fr = idx >> 2, c4 = (idx & 3) * 4;
                    float4 v = *reinterpret_cast<const float4*>(
                        &x[((size_t)b * FEAT + fb + fr) * NUM + n0 + c4]);
                    *reinterpret_cast<float4*>(&xb[fr * 16 + c4]) = v;
                }
            }
            const float* wc = &Wf[t * 4128 + lane * 129];
            const float* xc = &X4[(t & 1) * 2048];
            const int fw = w * 16;
#pragma unroll 4
            for (int fi = 0; fi < 16; fi++) {
                const int fl = fw + fi;
                float wv = wc[fl];                                // LDS32 cf
                ull   wp = pk(wv, wv);
                const ulonglong2* xr = reinterpret_cast<const ulonglong2*>(&xc[fl * 16]);
                ulonglong2 xa = xr[0];                            // LDS128 bc
                ulonglong2 xb = xr[1];
                ffma2(acc[0], wp, xa.x);
                ffma2(acc[1], wp, xa.y);
                ffma2(acc[2], wp, xb.x);
                ffma2(acc[3], wp, xb.y);
                xa = xr[2];
                xb = xr[3];
                ffma2(acc[4], wp, xa.x);
                ffma2(acc[5], wp, xa.y);
                ffma2(acc[6], wp, xb.x);
                ffma2(acc[7], wp, xb.y);
            }
        }

        __syncthreads();
        {
            float* r = &redf[(w * 32 + lane) * 17];
#pragma unroll
            for (int j = 0; j < 8; j++) {
                float f0, f1;
                upk(f0, f1, acc[j]);
                r[2 * j]     = f0;
                r[2 * j + 1] = f1;
            }
        }
        __syncthreads();

        {
            float l0 = 0.f, l1 = 0.f;
#pragma unroll
            for (int g = 0; g < 8; g++) {
                const float* r = &redf[(g * 32 + lane) * 17 + 2 * w];
                l0 += r[0];
                l1 += r[1];
            }
            const float bv = bias[lane];
            float pa;
            {
                float lg = l0 + bv;
                float m = wmax(lg);
                float e = __expf(lg - m);
                float s = wsum(e);
                float a = e / s;
                g_a[((size_t)b * NUM + n0 + 2 * w) * KK + lane] = a;
                pa = a;
            }
            {
                float lg = l1 + bv;
                float m = wmax(lg);
                float e = __expf(lg - m);
                float s = wsum(e);
                float a = e / s;
                g_a[((size_t)b * NUM + n0 + 2 * w + 1) * KK + lane] = a;
                pa += a;
            }
            asr[w * 33 + lane] = pa;
        }
        __syncthreads();
        if (tid < 32) {
            float s = 0.f;
#pragma unroll
            for (int g = 0; g < 8; g++) s += asr[g * 33 + tid];
            g_asumt[((size_t)b * KK + tid) * 32 + tile] = s;
        }
        __syncthreads();   // all P1 smem reads done before P2 overlay
    }

    // pre-barrier: stage X(u0) into Xs0 (input-only; overlays dead W region)
    {
        float* Xsf = reinterpret_cast<float*>(smx + 8448);
#pragma unroll
        for (int i = 0; i < 4; i++) {
            int idx = tid + i * 256;
            int fr = idx >> 4, nc = (idx & 15) * 4;
            float4 v = *reinterpret_cast<const float4*>(
                &x[((size_t)b0 * FEAT + ft0 * 64 + fr) * NUM + c0 * 64 + nc]);
            *reinterpret_cast<float4*>(&Xsf[fr * 68 + nc]) = v;
        }
    }

    gridbar();

    // ================= PHASE 2: 2 static units, fully pipelined ===============
    {
        const int fh = w & 1;
        const int kh = (w >> 1) & 1;
        const int nq = w >> 2;
        const int fgl = (fh << 5) + (lane >> 2);
        const int kbase = (kh << 4) + (lane & 3) * 4;

        // stage A(u0), then A(u1)+X(u1): all LDGs in flight before first sync
        p2_stage(smx, 0,     8448,  x, b0, ft0 * 64, c0 * 64, tid, false);
        p2_stage(smx, 25856, 34304, x, b1, ft1 * 64, c1 * 64, tid, true);
        __syncthreads();
        p2_compute(smx, 0, 8448, c0, ft0 * 64, b0, fgl, kbase, nq);
        __syncthreads();
        p2_compute(smx, 25856, 34304, c1, ft1 * 64, b1, fgl, kbase, nq);
    }

    gridbar();

    // ================= PHASE 3: fisher vectors + rownorm + const scale ========
    {
        const int b      = bx >> 5;
        const int fgbase = (bx & 31) * 2;

        // asum[b][k]: 32 contiguous partials -> 8x LDG.128
        float asv = 0.f;
        {
            const float4* p = reinterpret_cast<const float4*>(&g_asumt[((size_t)b * KK + lane) * 32]);
#pragma unroll
            for (int q = 0; q < 8; q++) {
                float4 v = p[q];
                asv += (v.x + v.y) + (v.z + v.w);
            }
        }

#pragma unroll
        for (int j = 0; j < 2; j++) {
            const int f = (fgbase + j) * 8 + w;
            float ax = 0.f, ax2 = 0.f;
#pragma unroll
            for (int s = 0; s < NSPLIT; s++) {
                size_t po = (((size_t)s * BATCH + b) * FEAT + f) * KK + lane;
                ax  += g_axp[po];
                ax2 += g_ax2p[po];
            }
            float muv = mu[f * KK + lane];
            float sg  = sigma[f * KK + lane];
            float fv1 = (ax - muv * asv) / sg;
            float fv2 = (ax2 - 2.f * muv * ax + muv * muv * asv) / (sg * sg) - asv;

            float n1 = sqrtf(wsum(fv1 * fv1));
            float n2 = sqrtf(wsum(fv2 * fv2));
            float v1 = fv1 / fmaxf(n1, 1e-12f) * GSC;
            float v2 = fv2 / fmaxf(n2, 1e-12f) * GSC;

            const size_t ob = (size_t)b * 2 * FEAT * KK;
            out[ob + (size_t)f * KK + lane]             = v1;
            out[ob + FEAT * KK + (size_t)f * KK + lane] = v2;
        }
    }
}

// ---------------- launch -----------------------------------------------------
extern "C" void kernel_launch(void* const* d_in, const int* in_sizes, int n_in,
                              void* d_out, int out_size) {
    (void)in_sizes; (void)n_in; (void)out_size;
    const float* x     = (const float*)d_in[0];
    const float* W     = (const float*)d_in[1];
    const float* bias  = (const float*)d_in[2];
    const float* mu    = (const float*)d_in[3];
    const float* sigma = (const float*)d_in[4];
    float* out = (float*)d_out;

    cudaFuncSetAttribute(k_all, cudaFuncAttributeMaxDynamicSharedMemorySize,
                         SMEM_BYTES);
    k_all<<<NBLK, 256, SMEM_BYTES>>>(x, W, bias, mu, sigma, out);
}